// round 7
// baseline (speedup 1.0000x reference)
#include <cuda_runtime.h>
#include <cuda_fp16.h>
#include <mma.h>
#include <math.h>

#define NATOMS 1048576
#define BMOL   16384
#define DIM    128
#define STEPS  8

// ---------------- scratch (static device arrays only) ----------------
__device__ float g_carry[BMOL * DIM];
__device__ float g_mem  [BMOL * DIM];
__device__ float g_cse  [BMOL * 2 * DIM];
__device__ float g_z    [BMOL * 4 * DIM];
__device__ int   g_segstart[BMOL + 1];
__device__ __half g_Fh[(size_t)NATOMS * DIM];  // 256 MB fp16 features
__device__ __half g_Wh[256 * 512];             // W hi fp16
__device__ __half g_Wl[256 * 512];             // W residual fp16

// ---------------- init ----------------
__global__ void init_state() {
    int i = blockIdx.x * blockDim.x + threadIdx.x;
    if (i < BMOL * DIM) { g_carry[i] = 0.f; g_mem[i] = 0.f; }
}

__global__ void seg_start_kernel(const int* __restrict__ idx) {
    int b = blockIdx.x * blockDim.x + threadIdx.x;
    if (b > BMOL) return;
    int lo = 0, hi = NATOMS;
    while (lo < hi) {
        int mid = (lo + hi) >> 1;
        if (idx[mid] < b) lo = mid + 1; else hi = mid;
    }
    g_segstart[b] = lo;
}

// W -> hi/lo fp16 split (once per call; tiny)
__global__ void wsplit_kernel(const float* __restrict__ W) {
    int i = blockIdx.x * blockDim.x + threadIdx.x;
    if (i >= 256 * 512) return;
    float v = W[i];
    __half h = __float2half_rn(v);
    g_Wh[i] = h;
    g_Wl[i] = __float2half_rn(v - __half2float(h));
}

__device__ __forceinline__ void h8_to_f(uint4 p, float* f) {
    float2 f0 = __half22float2(*(__half2*)&p.x);
    float2 f1 = __half22float2(*(__half2*)&p.y);
    float2 f2 = __half22float2(*(__half2*)&p.z);
    float2 f3 = __half22float2(*(__half2*)&p.w);
    f[0] = f0.x; f[1] = f0.y; f[2] = f1.x; f[3] = f1.y;
    f[4] = f2.x; f[5] = f2.y; f[6] = f3.x; f[7] = f3.y;
}

// ---------------- step 0: warp-per-molecule convert + segment mean -----------
// carry == 0 at step 0 -> softmax uniform -> readout = segment mean.
__global__ void __launch_bounds__(256) step0_kernel(
    const float4* __restrict__ F4, float* __restrict__ out) {
    int tid  = threadIdx.x;
    int lane = tid & 31;
    int wid  = tid >> 5;
    int b    = blockIdx.x * 8 + wid;
    if (b >= BMOL) return;

    int half_id = lane >> 4;
    int sub     = lane & 15;

    int s = g_segstart[b];
    int e = g_segstart[b + 1];
    int cnt = e - s;

    float4* orow = (float4*)(out + (size_t)b * 2 * DIM);
    if (cnt <= 0) {
        if (half_id == 0) {
            orow[sub * 2]     = make_float4(0, 0, 0, 0);
            orow[sub * 2 + 1] = make_float4(0, 0, 0, 0);
        } else {
            orow[32 + sub * 2]     = make_float4(0, 0, 0, 0);
            orow[32 + sub * 2 + 1] = make_float4(0, 0, 0, 0);
        }
        return;
    }

    float acc[8];
    #pragma unroll
    for (int k = 0; k < 8; k++) acc[k] = 0.f;

    for (int a0 = 0; a0 < cnt; a0 += 2) {
        int a = a0 + half_id;
        if (a < cnt) {
            size_t row = (size_t)(s + a);
            float4 va = F4[row * 32 + sub * 2];
            float4 vb = F4[row * 32 + sub * 2 + 1];
            __half2 h0 = __floats2half2_rn(va.x, va.y);
            __half2 h1 = __floats2half2_rn(va.z, va.w);
            __half2 h2 = __floats2half2_rn(vb.x, vb.y);
            __half2 h3 = __floats2half2_rn(vb.z, vb.w);
            uint4 o;
            o.x = *(unsigned*)&h0; o.y = *(unsigned*)&h1;
            o.z = *(unsigned*)&h2; o.w = *(unsigned*)&h3;
            ((uint4*)g_Fh)[row * 16 + sub] = o;
            acc[0] += va.x; acc[1] += va.y; acc[2] += va.z; acc[3] += va.w;
            acc[4] += vb.x; acc[5] += vb.y; acc[6] += vb.z; acc[7] += vb.w;
        }
    }
    #pragma unroll
    for (int k = 0; k < 8; k++) acc[k] += __shfl_xor_sync(0xffffffffu, acc[k], 16);

    float invc = 1.0f / (float)cnt;
    if (half_id == 0) {
        orow[sub * 2]     = make_float4(0, 0, 0, 0);
        orow[sub * 2 + 1] = make_float4(0, 0, 0, 0);
    } else {
        orow[32 + sub * 2]     = make_float4(acc[0] * invc, acc[1] * invc,
                                             acc[2] * invc, acc[3] * invc);
        orow[32 + sub * 2 + 1] = make_float4(acc[4] * invc, acc[5] * invc,
                                             acc[6] * invc, acc[7] * invc);
    }
}

// ---------------- warp-per-molecule online-softmax attention ----------------
__global__ void __launch_bounds__(256) attn_kernel(float* __restrict__ out) {
    int tid  = threadIdx.x;
    int lane = tid & 31;
    int wid  = tid >> 5;
    int b    = blockIdx.x * 8 + wid;
    if (b >= BMOL) return;

    int half_id = lane >> 4;
    int sub     = lane & 15;

    int s = g_segstart[b];
    int e = g_segstart[b + 1];
    int cnt = e - s;

    // carry for this lane's 8 dims
    const float4* crow = (const float4*)(g_carry + (size_t)b * DIM);
    float4 ca = crow[sub * 2];
    float4 cb = crow[sub * 2 + 1];
    float c8[8] = {ca.x, ca.y, ca.z, ca.w, cb.x, cb.y, cb.z, cb.w};

    float4* orow = (float4*)(out + (size_t)b * 2 * DIM);
    if (cnt <= 0) {
        if (half_id == 0) {
            orow[sub * 2]     = ca;
            orow[sub * 2 + 1] = cb;
        } else {
            orow[32 + sub * 2]     = make_float4(0, 0, 0, 0);
            orow[32 + sub * 2 + 1] = make_float4(0, 0, 0, 0);
        }
        return;
    }

    const uint4* F4h = (const uint4*)g_Fh;   // 16 uint4 per atom row

    float m = -INFINITY, ssum = 0.f;
    float acc[8];
    #pragma unroll
    for (int k = 0; k < 8; k++) acc[k] = 0.f;

    for (int a0 = 0; a0 < cnt; a0 += 2) {
        int a = a0 + half_id;
        bool valid = (a < cnt);
        float v = 0.f;
        float f[8];
        if (valid) {
            uint4 p = F4h[(size_t)(s + a) * 16 + sub];
            h8_to_f(p, f);
            #pragma unroll
            for (int k = 0; k < 8; k++) v += f[k] * c8[k];
        }
        #pragma unroll
        for (int o = 8; o > 0; o >>= 1) v += __shfl_xor_sync(0xffffffffu, v, o);
        if (valid) {
            float nm   = fmaxf(m, v);
            float scl  = expf(m - nm);      // 0 on first iteration (m=-inf)
            float pexp = expf(v - nm);
            ssum = ssum * scl + pexp;
            #pragma unroll
            for (int k = 0; k < 8; k++) acc[k] = acc[k] * scl + pexp * f[k];
            m = nm;
        }
    }

    // combine the two half-warps (disjoint atoms, same dims)
    float m_o = __shfl_xor_sync(0xffffffffu, m, 16);
    float s_o = __shfl_xor_sync(0xffffffffu, ssum, 16);
    float M2  = fmaxf(m, m_o);
    float sa  = (m   > -INFINITY) ? expf(m   - M2) : 0.f;
    float sb  = (m_o > -INFINITY) ? expf(m_o - M2) : 0.f;
    float S   = ssum * sa + s_o * sb;
    float invS = 1.0f / S;
    #pragma unroll
    for (int k = 0; k < 8; k++) {
        float ao = __shfl_xor_sync(0xffffffffu, acc[k], 16);
        acc[k] = (acc[k] * sa + ao * sb) * invS;
    }

    if (half_id == 0) {
        orow[sub * 2]     = ca;
        orow[sub * 2 + 1] = cb;
    } else {
        orow[32 + sub * 2]     = make_float4(acc[0], acc[1], acc[2], acc[3]);
        orow[32 + sub * 2 + 1] = make_float4(acc[4], acc[5], acc[6], acc[7]);
    }
}

// ---------------- fp16-split GEMM: g_z = X[BMOL,256] @ W[256,512] -------------
// X split in-kernel, W split precomputed. z = Xh*Wh + Xh*Wl + Xl*Wh (fp32 acc).
using namespace nvcuda;
#define GEMM_THREADS 256
#define A_LDH 40                 // 32 + 8 pad (halves)
#define B_LDH 136                // 128 + 8 pad (halves)
#define AH_SZ (128 * A_LDH)
#define BH_SZ (32 * B_LDH)
#define GEMM_SMEM ((2 * AH_SZ + 2 * BH_SZ) * sizeof(__half))

__global__ void __launch_bounds__(GEMM_THREADS, 2) gemm_kernel(
    const float4* __restrict__ X4) {
    int bm = blockIdx.x * 128;
    int bn = blockIdx.y * 128;

    extern __shared__ __half smh[];
    __half* Ah = smh;
    __half* Al = Ah + AH_SZ;
    __half* Bh = Al + AH_SZ;
    __half* Bl = Bh + BH_SZ;

    wmma::fragment<wmma::accumulator, 16, 16, 16, float> acc[2][4];
    #pragma unroll
    for (int i = 0; i < 2; i++)
        #pragma unroll
        for (int j = 0; j < 4; j++) wmma::fill_fragment(acc[i][j], 0.f);

    int wid = threadIdx.x >> 5;
    int wm = (wid >> 1) * 32;
    int wn = (wid & 1) * 64;

    for (int k0 = 0; k0 < 256; k0 += 32) {
        // A tile: 128 x 32 floats -> hi/lo halves (half2 stores)
        for (int i = threadIdx.x; i < 128 * 8; i += GEMM_THREADS) {
            int r = i >> 3, c = i & 7;
            float4 v = X4[(size_t)(bm + r) * 64 + (k0 >> 2) + c];
            __half2 hx = __floats2half2_rn(v.x, v.y);
            __half2 hz = __floats2half2_rn(v.z, v.w);
            float2 fx = __half22float2(hx);
            float2 fz = __half22float2(hz);
            __half2 lx = __floats2half2_rn(v.x - fx.x, v.y - fx.y);
            __half2 lz = __floats2half2_rn(v.z - fz.x, v.w - fz.y);
            *(__half2*)(Ah + r * A_LDH + c * 4)     = hx;
            *(__half2*)(Ah + r * A_LDH + c * 4 + 2) = hz;
            *(__half2*)(Al + r * A_LDH + c * 4)     = lx;
            *(__half2*)(Al + r * A_LDH + c * 4 + 2) = lz;
        }
        // B tile: 32 x 128 halves, direct from precomputed split (uint4 = 8 halves)
        for (int i = threadIdx.x; i < 32 * 16; i += GEMM_THREADS) {
            int r = i >> 4, c = i & 15;
            size_t gidx = ((size_t)(k0 + r) * 512 + bn) / 8 + c;
            *(uint4*)(Bh + r * B_LDH + c * 8) = ((const uint4*)g_Wh)[gidx];
            *(uint4*)(Bl + r * B_LDH + c * 8) = ((const uint4*)g_Wl)[gidx];
        }
        __syncthreads();

        #pragma unroll
        for (int kk = 0; kk < 32; kk += 16) {
            wmma::fragment<wmma::matrix_a, 16, 16, 16, __half, wmma::row_major> ah[2], al[2];
            wmma::fragment<wmma::matrix_b, 16, 16, 16, __half, wmma::row_major> bh[4], bl[4];
            #pragma unroll
            for (int i = 0; i < 2; i++) {
                wmma::load_matrix_sync(ah[i], &Ah[(wm + i * 16) * A_LDH + kk], A_LDH);
                wmma::load_matrix_sync(al[i], &Al[(wm + i * 16) * A_LDH + kk], A_LDH);
            }
            #pragma unroll
            for (int j = 0; j < 4; j++) {
                wmma::load_matrix_sync(bh[j], &Bh[kk * B_LDH + wn + j * 16], B_LDH);
                wmma::load_matrix_sync(bl[j], &Bl[kk * B_LDH + wn + j * 16], B_LDH);
            }
            #pragma unroll
            for (int i = 0; i < 2; i++)
                #pragma unroll
                for (int j = 0; j < 4; j++) {
                    wmma::mma_sync(acc[i][j], ah[i], bh[j], acc[i][j]);
                    wmma::mma_sync(acc[i][j], ah[i], bl[j], acc[i][j]);
                    wmma::mma_sync(acc[i][j], al[i], bh[j], acc[i][j]);
                }
        }
        __syncthreads();
    }

    #pragma unroll
    for (int i = 0; i < 2; i++)
        #pragma unroll
        for (int j = 0; j < 4; j++)
            wmma::store_matrix_sync(&g_z[(size_t)(bm + wm + i * 16) * 512 + bn + wn + j * 16],
                                    acc[i][j], 512, wmma::mem_row_major);
}

// ---------------- LSTM pointwise (float4 vectorized) ----------------
__global__ void lstm_kernel(const float4* __restrict__ bias4) {
    int p = blockIdx.x * blockDim.x + threadIdx.x;
    if (p >= BMOL * 32) return;
    int b = p >> 5;
    int q = p & 31;
    const float4* zr = (const float4*)(g_z + (size_t)b * 512);
    float4 u4 = zr[q];
    float4 f4 = zr[32 + q];
    float4 c4 = zr[64 + q];
    float4 o4 = zr[96 + q];
    float4 bu = bias4[q], bf = bias4[32 + q], bc = bias4[64 + q], bo = bias4[96 + q];
    float4 m4 = ((const float4*)g_mem)[(size_t)b * 32 + q];

    float un[4] = {u4.x + bu.x, u4.y + bu.y, u4.z + bu.z, u4.w + bu.w};
    float fn[4] = {f4.x + bf.x, f4.y + bf.y, f4.z + bf.z, f4.w + bf.w};
    float cn[4] = {c4.x + bc.x, c4.y + bc.y, c4.z + bc.z, c4.w + bc.w};
    float on[4] = {o4.x + bo.x, o4.y + bo.y, o4.z + bo.z, o4.w + bo.w};
    float mm[4] = {m4.x, m4.y, m4.z, m4.w};
    float nm[4], cy[4];
    #pragma unroll
    for (int k = 0; k < 4; k++) {
        float su = 1.f / (1.f + expf(-un[k]));
        float sf = 1.f / (1.f + expf(-fn[k]));
        float so = 1.f / (1.f + expf(-on[k]));
        nm[k] = sf * mm[k] + su * tanhf(cn[k]);
        cy[k] = so * tanhf(nm[k]);
    }
    ((float4*)g_mem)[(size_t)b * 32 + q]   = make_float4(nm[0], nm[1], nm[2], nm[3]);
    ((float4*)g_carry)[(size_t)b * 32 + q] = make_float4(cy[0], cy[1], cy[2], cy[3]);
}

// ---------------- launch ----------------
extern "C" void kernel_launch(void* const* d_in, const int* in_sizes, int n_in,
                              void* d_out, int out_size) {
    const float* F    = (const float*)d_in[0];
    const int*   idx  = (const int*)d_in[1];
    const float* W    = (const float*)d_in[2];
    const float* bias = (const float*)d_in[3];
    float* out = (float*)d_out;

    static bool attr_done = false;
    if (!attr_done) {
        cudaFuncSetAttribute(gemm_kernel, cudaFuncAttributeMaxDynamicSharedMemorySize,
                             (int)GEMM_SMEM);
        attr_done = true;
    }

    void* csep = nullptr;
    cudaGetSymbolAddress(&csep, g_cse);
    float* cse = (float*)csep;

    init_state<<<(BMOL * DIM + 255) / 256, 256>>>();
    seg_start_kernel<<<(BMOL + 1 + 255) / 256, 256>>>(idx);
    wsplit_kernel<<<(256 * 512 + 255) / 256, 256>>>(W);

    dim3 gg(BMOL / 128, 4);

    // t = 0: convert + mean readout (carry == 0)
    step0_kernel<<<BMOL / 8, 256>>>((const float4*)F, cse);
    gemm_kernel<<<gg, GEMM_THREADS, GEMM_SMEM>>>((const float4*)cse);
    lstm_kernel<<<(BMOL * 32 + 255) / 256, 256>>>((const float4*)bias);

    for (int t = 1; t < STEPS; t++) {
        float* o = (t == STEPS - 1) ? out : cse;
        attn_kernel<<<BMOL / 8, 256>>>(o);
        if (t < STEPS - 1) {
            gemm_kernel<<<gg, GEMM_THREADS, GEMM_SMEM>>>((const float4*)cse);
            lstm_kernel<<<(BMOL * 32 + 255) / 256, 256>>>((const float4*)bias);
        }
    }
}

// round 8
// speedup vs baseline: 1.2657x; 1.2657x over previous
#include <cuda_runtime.h>
#include <cuda_fp16.h>
#include <mma.h>
#include <math.h>

#define NATOMS 1048576
#define BMOL   16384
#define DIM    128
#define STEPS  8

// ---------------- scratch (static device arrays only) ----------------
__device__ float  g_carry[BMOL * DIM];
__device__ float  g_mem  [BMOL * DIM];
__device__ float  g_z    [BMOL * 4 * DIM];
__device__ int    g_segstart[BMOL + 1];
__device__ __half g_Fh[(size_t)NATOMS * DIM];  // 256 MB fp16 features
__device__ __half g_Wh[256 * 512];             // W hi fp16
__device__ __half g_Wl[256 * 512];             // W residual fp16
__device__ __half g_Xh[BMOL * 256];            // GEMM input hi fp16  [carry|readout]
__device__ __half g_Xl[BMOL * 256];            // GEMM input lo fp16

// ---------------- init ----------------
__global__ void init_state() {
    int i = blockIdx.x * blockDim.x + threadIdx.x;
    if (i < BMOL * DIM) { g_carry[i] = 0.f; g_mem[i] = 0.f; }
}

__global__ void seg_start_kernel(const int* __restrict__ idx) {
    int b = blockIdx.x * blockDim.x + threadIdx.x;
    if (b > BMOL) return;
    int lo = 0, hi = NATOMS;
    while (lo < hi) {
        int mid = (lo + hi) >> 1;
        if (idx[mid] < b) lo = mid + 1; else hi = mid;
    }
    g_segstart[b] = lo;
}

__global__ void wsplit_kernel(const float* __restrict__ W) {
    int i = blockIdx.x * blockDim.x + threadIdx.x;
    if (i >= 256 * 512) return;
    float v = W[i];
    __half h = __float2half_rn(v);
    g_Wh[i] = h;
    g_Wl[i] = __float2half_rn(v - __half2float(h));
}

__device__ __forceinline__ void h8_to_f(uint4 p, float* f) {
    float2 f0 = __half22float2(*(__half2*)&p.x);
    float2 f1 = __half22float2(*(__half2*)&p.y);
    float2 f2 = __half22float2(*(__half2*)&p.z);
    float2 f3 = __half22float2(*(__half2*)&p.w);
    f[0] = f0.x; f[1] = f0.y; f[2] = f1.x; f[3] = f1.y;
    f[4] = f2.x; f[5] = f2.y; f[6] = f3.x; f[7] = f3.y;
}

// pack 8 floats into hi/lo fp16 uint4s
__device__ __forceinline__ void f8_to_hl(const float* a, uint4& hi, uint4& lo) {
    __half2 h0 = __floats2half2_rn(a[0], a[1]);
    __half2 h1 = __floats2half2_rn(a[2], a[3]);
    __half2 h2 = __floats2half2_rn(a[4], a[5]);
    __half2 h3 = __floats2half2_rn(a[6], a[7]);
    float2 g0 = __half22float2(h0), g1 = __half22float2(h1);
    float2 g2 = __half22float2(h2), g3 = __half22float2(h3);
    __half2 l0 = __floats2half2_rn(a[0] - g0.x, a[1] - g0.y);
    __half2 l1 = __floats2half2_rn(a[2] - g1.x, a[3] - g1.y);
    __half2 l2 = __floats2half2_rn(a[4] - g2.x, a[5] - g2.y);
    __half2 l3 = __floats2half2_rn(a[6] - g3.x, a[7] - g3.y);
    hi.x = *(unsigned*)&h0; hi.y = *(unsigned*)&h1;
    hi.z = *(unsigned*)&h2; hi.w = *(unsigned*)&h3;
    lo.x = *(unsigned*)&l0; lo.y = *(unsigned*)&l1;
    lo.z = *(unsigned*)&l2; lo.w = *(unsigned*)&l3;
}

// ---------------- step 0: warp-per-molecule convert + segment mean -----------
// carry == 0 -> softmax uniform -> readout = segment mean. Writes X halves.
__global__ void __launch_bounds__(256) step0_kernel(const float4* __restrict__ F4) {
    int tid  = threadIdx.x;
    int lane = tid & 31;
    int wid  = tid >> 5;
    int b    = blockIdx.x * 8 + wid;
    if (b >= BMOL) return;

    int half_id = lane >> 4;
    int sub     = lane & 15;

    int s = g_segstart[b];
    int e = g_segstart[b + 1];
    int cnt = e - s;

    uint4* xh = (uint4*)g_Xh + (size_t)b * 32;   // 32 uint4 per 256-half row
    uint4* xl = (uint4*)g_Xl + (size_t)b * 32;
    uint4 z4 = make_uint4(0, 0, 0, 0);

    if (cnt <= 0) {
        int o = half_id * 16 + sub;
        xh[o] = z4; xl[o] = z4;
        return;
    }

    float acc[8];
    #pragma unroll
    for (int k = 0; k < 8; k++) acc[k] = 0.f;

    for (int a0 = 0; a0 < cnt; a0 += 2) {
        int a = a0 + half_id;
        if (a < cnt) {
            size_t row = (size_t)(s + a);
            float4 va = F4[row * 32 + sub * 2];
            float4 vb = F4[row * 32 + sub * 2 + 1];
            __half2 h0 = __floats2half2_rn(va.x, va.y);
            __half2 h1 = __floats2half2_rn(va.z, va.w);
            __half2 h2 = __floats2half2_rn(vb.x, vb.y);
            __half2 h3 = __floats2half2_rn(vb.z, vb.w);
            uint4 o;
            o.x = *(unsigned*)&h0; o.y = *(unsigned*)&h1;
            o.z = *(unsigned*)&h2; o.w = *(unsigned*)&h3;
            ((uint4*)g_Fh)[row * 16 + sub] = o;
            acc[0] += va.x; acc[1] += va.y; acc[2] += va.z; acc[3] += va.w;
            acc[4] += vb.x; acc[5] += vb.y; acc[6] += vb.z; acc[7] += vb.w;
        }
    }
    #pragma unroll
    for (int k = 0; k < 8; k++) acc[k] += __shfl_xor_sync(0xffffffffu, acc[k], 16);

    float invc = 1.0f / (float)cnt;
    #pragma unroll
    for (int k = 0; k < 8; k++) acc[k] *= invc;

    if (half_id == 0) {
        xh[sub] = z4; xl[sub] = z4;            // carry = 0
    } else {
        uint4 hi, lo;
        f8_to_hl(acc, hi, lo);
        xh[16 + sub] = hi; xl[16 + sub] = lo;
    }
}

// ---------------- warp-per-molecule online-softmax attention (MLP x4) --------
__global__ void __launch_bounds__(256) attn_kernel(float* __restrict__ out, int final_step) {
    int tid  = threadIdx.x;
    int lane = tid & 31;
    int wid  = tid >> 5;
    int b    = blockIdx.x * 8 + wid;
    if (b >= BMOL) return;

    int half_id = lane >> 4;
    int sub     = lane & 15;

    int s = g_segstart[b];
    int e = g_segstart[b + 1];
    int cnt = e - s;

    const float4* crow = (const float4*)(g_carry + (size_t)b * DIM);
    float4 ca = crow[sub * 2];
    float4 cb = crow[sub * 2 + 1];
    float c8[8] = {ca.x, ca.y, ca.z, ca.w, cb.x, cb.y, cb.z, cb.w};

    float m = -INFINITY, ssum = 0.f;
    float acc[8];
    #pragma unroll
    for (int k = 0; k < 8; k++) acc[k] = 0.f;

    const uint4* F4h = (const uint4*)g_Fh;

    if (cnt > 0) {
        int cnt8 = cnt & ~7;
        int a0 = 0;
        for (; a0 < cnt8; a0 += 8) {
            float f[4][8], v[4];
            #pragma unroll
            for (int j = 0; j < 4; j++) {
                int a = a0 + 2 * j + half_id;
                uint4 p = F4h[(size_t)(s + a) * 16 + sub];
                h8_to_f(p, f[j]);
                float vv = 0.f;
                #pragma unroll
                for (int k = 0; k < 8; k++) vv += f[j][k] * c8[k];
                v[j] = vv;
            }
            #pragma unroll
            for (int j = 0; j < 4; j++) {
                #pragma unroll
                for (int o = 8; o > 0; o >>= 1)
                    v[j] += __shfl_xor_sync(0xffffffffu, v[j], o);
            }
            #pragma unroll
            for (int j = 0; j < 4; j++) {
                float nm   = fmaxf(m, v[j]);
                float scl  = expf(m - nm);
                float pexp = expf(v[j] - nm);
                ssum = ssum * scl + pexp;
                #pragma unroll
                for (int k = 0; k < 8; k++) acc[k] = acc[k] * scl + pexp * f[j][k];
                m = nm;
            }
        }
        for (; a0 < cnt; a0 += 2) {
            int a = a0 + half_id;
            bool valid = (a < cnt);
            float v = 0.f, f[8];
            if (valid) {
                uint4 p = F4h[(size_t)(s + a) * 16 + sub];
                h8_to_f(p, f);
                #pragma unroll
                for (int k = 0; k < 8; k++) v += f[k] * c8[k];
            }
            #pragma unroll
            for (int o = 8; o > 0; o >>= 1) v += __shfl_xor_sync(0xffffffffu, v, o);
            if (valid) {
                float nm   = fmaxf(m, v);
                float scl  = expf(m - nm);
                float pexp = expf(v - nm);
                ssum = ssum * scl + pexp;
                #pragma unroll
                for (int k = 0; k < 8; k++) acc[k] = acc[k] * scl + pexp * f[k];
                m = nm;
            }
        }

        // combine half-warps
        float m_o = __shfl_xor_sync(0xffffffffu, m, 16);
        float s_o = __shfl_xor_sync(0xffffffffu, ssum, 16);
        float M2  = fmaxf(m, m_o);
        float sa  = (m   > -INFINITY) ? expf(m   - M2) : 0.f;
        float sb  = (m_o > -INFINITY) ? expf(m_o - M2) : 0.f;
        float S    = ssum * sa + s_o * sb;
        float invS = 1.0f / S;
        #pragma unroll
        for (int k = 0; k < 8; k++) {
            float ao = __shfl_xor_sync(0xffffffffu, acc[k], 16);
            acc[k] = (acc[k] * sa + ao * sb) * invS;
        }
    }

    if (final_step) {
        float4* orow = (float4*)(out + (size_t)b * 2 * DIM);
        if (half_id == 0) {
            orow[sub * 2]     = ca;
            orow[sub * 2 + 1] = cb;
        } else {
            orow[32 + sub * 2]     = make_float4(acc[0], acc[1], acc[2], acc[3]);
            orow[32 + sub * 2 + 1] = make_float4(acc[4], acc[5], acc[6], acc[7]);
        }
    } else if (half_id == 1) {
        // write readout halves as hi/lo fp16 (carry halves written by lstm)
        uint4 hi, lo;
        f8_to_hl(acc, hi, lo);
        ((uint4*)g_Xh)[(size_t)b * 32 + 16 + sub] = hi;
        ((uint4*)g_Xl)[(size_t)b * 32 + 16 + sub] = lo;
    }
}

// ---------------- cp.async pipelined fp16-split GEMM -------------------------
// g_z = X[BMOL,256] @ W[256,512]; X,W pre-split hi/lo fp16; fp32 accumulate.
using namespace nvcuda;
#define GEMM_THREADS 256
#define A_LDH 40
#define B_LDH 136
#define AH_SZ (128 * A_LDH)
#define BH_SZ (32 * B_LDH)
#define STAGE_HALVES (2 * AH_SZ + 2 * BH_SZ)
#define GEMM_SMEM (2 * STAGE_HALVES * sizeof(__half))

__device__ __forceinline__ void cp16(void* smem, const void* gmem) {
    unsigned saddr = (unsigned)__cvta_generic_to_shared(smem);
    asm volatile("cp.async.cg.shared.global [%0], [%1], 16;" :: "r"(saddr), "l"(gmem));
}

__global__ void __launch_bounds__(GEMM_THREADS, 2) gemm_kernel() {
    int bm = blockIdx.x * 128;
    int bn = blockIdx.y * 128;
    int tid = threadIdx.x;

    extern __shared__ __half smh[];

    wmma::fragment<wmma::accumulator, 16, 16, 16, float> acc[2][4];
    #pragma unroll
    for (int i = 0; i < 2; i++)
        #pragma unroll
        for (int j = 0; j < 4; j++) wmma::fill_fragment(acc[i][j], 0.f);

    int wid = tid >> 5;
    int wm = (wid >> 1) * 32;
    int wn = (wid & 1) * 64;

    // stage loader: A 128x32 halves (hi+lo), B 32x128 halves (hi+lo)
    auto load_stage = [&](int stg, int k0) {
        __half* Ah = smh + stg * STAGE_HALVES;
        __half* Al = Ah + AH_SZ;
        __half* Bh = Al + AH_SZ;
        __half* Bl = Bh + BH_SZ;
        #pragma unroll
        for (int i = tid; i < 512; i += GEMM_THREADS) {   // A: r=i>>2, c=i&3
            int r = i >> 2, c = i & 3;
            size_t g = (size_t)(bm + r) * 256 + k0 + c * 8;
            cp16(Ah + r * A_LDH + c * 8, g_Xh + g);
            cp16(Al + r * A_LDH + c * 8, g_Xl + g);
        }
        #pragma unroll
        for (int i = tid; i < 512; i += GEMM_THREADS) {   // B: r=i>>4, c=i&15
            int r = i >> 4, c = i & 15;
            size_t g = (size_t)(k0 + r) * 512 + bn + c * 8;
            cp16(Bh + r * B_LDH + c * 8, g_Wh + g);
            cp16(Bl + r * B_LDH + c * 8, g_Wl + g);
        }
        asm volatile("cp.async.commit_group;");
    };

    load_stage(0, 0);

    for (int ks = 0; ks < 8; ks++) {
        if (ks < 7) {
            load_stage((ks + 1) & 1, (ks + 1) * 32);
            asm volatile("cp.async.wait_group 1;");
        } else {
            asm volatile("cp.async.wait_group 0;");
        }
        __syncthreads();

        __half* Ah = smh + (ks & 1) * STAGE_HALVES;
        __half* Al = Ah + AH_SZ;
        __half* Bh = Al + AH_SZ;
        __half* Bl = Bh + BH_SZ;

        #pragma unroll
        for (int kk = 0; kk < 32; kk += 16) {
            wmma::fragment<wmma::matrix_a, 16, 16, 16, __half, wmma::row_major> ah[2], al[2];
            wmma::fragment<wmma::matrix_b, 16, 16, 16, __half, wmma::row_major> bh[4], bl[4];
            #pragma unroll
            for (int i = 0; i < 2; i++) {
                wmma::load_matrix_sync(ah[i], &Ah[(wm + i * 16) * A_LDH + kk], A_LDH);
                wmma::load_matrix_sync(al[i], &Al[(wm + i * 16) * A_LDH + kk], A_LDH);
            }
            #pragma unroll
            for (int j = 0; j < 4; j++) {
                wmma::load_matrix_sync(bh[j], &Bh[kk * B_LDH + wn + j * 16], B_LDH);
                wmma::load_matrix_sync(bl[j], &Bl[kk * B_LDH + wn + j * 16], B_LDH);
            }
            #pragma unroll
            for (int i = 0; i < 2; i++)
                #pragma unroll
                for (int j = 0; j < 4; j++) {
                    wmma::mma_sync(acc[i][j], ah[i], bh[j], acc[i][j]);
                    wmma::mma_sync(acc[i][j], ah[i], bl[j], acc[i][j]);
                    wmma::mma_sync(acc[i][j], al[i], bh[j], acc[i][j]);
                }
        }
        __syncthreads();
    }

    #pragma unroll
    for (int i = 0; i < 2; i++)
        #pragma unroll
        for (int j = 0; j < 4; j++)
            wmma::store_matrix_sync(&g_z[(size_t)(bm + wm + i * 16) * 512 + bn + wn + j * 16],
                                    acc[i][j], 512, wmma::mem_row_major);
}

// ---------------- LSTM pointwise (writes fp32 carry + X carry halves) --------
__global__ void lstm_kernel(const float4* __restrict__ bias4) {
    int p = blockIdx.x * blockDim.x + threadIdx.x;
    if (p >= BMOL * 32) return;
    int b = p >> 5;
    int q = p & 31;
    const float4* zr = (const float4*)(g_z + (size_t)b * 512);
    float4 u4 = zr[q];
    float4 f4 = zr[32 + q];
    float4 c4 = zr[64 + q];
    float4 o4 = zr[96 + q];
    float4 bu = bias4[q], bf = bias4[32 + q], bc = bias4[64 + q], bo = bias4[96 + q];
    float4 m4 = ((const float4*)g_mem)[(size_t)b * 32 + q];

    float un[4] = {u4.x + bu.x, u4.y + bu.y, u4.z + bu.z, u4.w + bu.w};
    float fn[4] = {f4.x + bf.x, f4.y + bf.y, f4.z + bf.z, f4.w + bf.w};
    float cn[4] = {c4.x + bc.x, c4.y + bc.y, c4.z + bc.z, c4.w + bc.w};
    float on[4] = {o4.x + bo.x, o4.y + bo.y, o4.z + bo.z, o4.w + bo.w};
    float mm[4] = {m4.x, m4.y, m4.z, m4.w};
    float nm[4], cy[4];
    #pragma unroll
    for (int k = 0; k < 4; k++) {
        float su = 1.f / (1.f + expf(-un[k]));
        float sf = 1.f / (1.f + expf(-fn[k]));
        float so = 1.f / (1.f + expf(-on[k]));
        nm[k] = sf * mm[k] + su * tanhf(cn[k]);
        cy[k] = so * tanhf(nm[k]);
    }
    ((float4*)g_mem)[(size_t)b * 32 + q]   = make_float4(nm[0], nm[1], nm[2], nm[3]);
    ((float4*)g_carry)[(size_t)b * 32 + q] = make_float4(cy[0], cy[1], cy[2], cy[3]);

    // hi/lo fp16 carry into X row (dims q*4..q*4+3)
    __half2 h01 = __floats2half2_rn(cy[0], cy[1]);
    __half2 h23 = __floats2half2_rn(cy[2], cy[3]);
    float2 g01 = __half22float2(h01), g23 = __half22float2(h23);
    __half2 l01 = __floats2half2_rn(cy[0] - g01.x, cy[1] - g01.y);
    __half2 l23 = __floats2half2_rn(cy[2] - g23.x, cy[3] - g23.y);
    uint2 hv, lv;
    hv.x = *(unsigned*)&h01; hv.y = *(unsigned*)&h23;
    lv.x = *(unsigned*)&l01; lv.y = *(unsigned*)&l23;
    ((uint2*)(g_Xh + (size_t)b * 256))[q] = hv;
    ((uint2*)(g_Xl + (size_t)b * 256))[q] = lv;
}

// ---------------- launch ----------------
extern "C" void kernel_launch(void* const* d_in, const int* in_sizes, int n_in,
                              void* d_out, int out_size) {
    const float* F    = (const float*)d_in[0];
    const int*   idx  = (const int*)d_in[1];
    const float* W    = (const float*)d_in[2];
    const float* bias = (const float*)d_in[3];
    float* out = (float*)d_out;

    static bool attr_done = false;
    if (!attr_done) {
        cudaFuncSetAttribute(gemm_kernel, cudaFuncAttributeMaxDynamicSharedMemorySize,
                             (int)GEMM_SMEM);
        attr_done = true;
    }

    init_state<<<(BMOL * DIM + 255) / 256, 256>>>();
    seg_start_kernel<<<(BMOL + 1 + 255) / 256, 256>>>(idx);
    wsplit_kernel<<<(256 * 512 + 255) / 256, 256>>>(W);

    dim3 gg(BMOL / 128, 4);

    // t = 0: convert + mean readout (carry == 0)
    step0_kernel<<<BMOL / 8, 256>>>((const float4*)F);
    gemm_kernel<<<gg, GEMM_THREADS, GEMM_SMEM>>>();
    lstm_kernel<<<(BMOL * 32 + 255) / 256, 256>>>((const float4*)bias);

    for (int t = 1; t < STEPS; t++) {
        attn_kernel<<<BMOL / 8, 256>>>(out, (t == STEPS - 1) ? 1 : 0);
        if (t < STEPS - 1) {
            gemm_kernel<<<gg, GEMM_THREADS, GEMM_SMEM>>>();
            lstm_kernel<<<(BMOL * 32 + 255) / 256, 256>>>((const float4*)bias);
        }
    }
}